// round 6
// baseline (speedup 1.0000x reference)
#include <cuda_runtime.h>
#include <cstdint>

#define FULLMASK 0xffffffffu

constexpr int T_ = 256;
constexpr int C_ = 128;
constexpr int L_ = 32;
constexpr int BLANK = 127;   // C-1
constexpr float EPSF = 1e-7f;
constexpr int EPW = 2;       // batch elements per warp (ILP)
constexpr int DEPTH = 8;     // register prefetch depth (rows ahead)

// One warp per block; each warp owns 2 batch elements.
// Lane i owns states s=i (aLo) and s=32+i (aHi); lane 31 also owns s=64 (aTop).
// Probability-domain alphas (fp32), rescale every 4 steps, applied 2 steps later.
// Emission gathers: per-lane indices are FIXED across t, so each lane streams its
// own 3 scalars per element straight from GMEM through an 8-deep register ring.
__global__ __launch_bounds__(32)
void ctc_alpha_kernel(const int* __restrict__ y_true_i32,
                      const float* __restrict__ y_pred,
                      float* __restrict__ out)
{
    const int lane = threadIdx.x;          // blockDim.x == 32
    const int b0   = blockIdx.x * EPW;
    const int b1   = b0 + 1;

    const float* row0 = y_pred + (size_t)b0 * T_ * C_;
    const float* row1 = y_pred + (size_t)b1 * T_ * C_;

    // ---- label dtype detection (int32 vs int64 low-word); first 32 words in-bounds
    int w0 = y_true_i32[lane];
    unsigned zmask = __ballot_sync(FULLMASK, w0 == 0);
    bool is64 = ((zmask & 0xAAAAAAAAu) == 0xAAAAAAAAu);

    int lab0 = is64 ? y_true_i32[((size_t)b0 * L_ + lane) * 2]
                    : y_true_i32[(size_t)b0 * L_ + lane];
    int lab1 = is64 ? y_true_i32[((size_t)b1 * L_ + lane) * 2]
                    : y_true_i32[(size_t)b1 * L_ + lane];
    lab0 &= 127; lab1 &= 127;

    // ---- extended-label class + skip permission
    const bool odd = (lane & 1);
    const int  kLo = (lane >= 1) ? ((lane - 1) >> 1) : 0;
    const int  kLp = (kLo >= 1) ? (kLo - 1) : 0;
    const int  kHi = (31 + lane) >> 1;
    const int  kHp = kHi - 1;

    int labLo0 = __shfl_sync(FULLMASK, lab0, kLo);
    int labLp0 = __shfl_sync(FULLMASK, lab0, kLp);
    int labHi0 = __shfl_sync(FULLMASK, lab0, kHi);
    int labHp0 = __shfl_sync(FULLMASK, lab0, kHp);
    int labLo1 = __shfl_sync(FULLMASK, lab1, kLo);
    int labLp1 = __shfl_sync(FULLMASK, lab1, kLp);
    int labHi1 = __shfl_sync(FULLMASK, lab1, kHi);
    int labHp1 = __shfl_sync(FULLMASK, lab1, kHp);

    const int   extLo0  = odd ? labLo0 : BLANK;
    const int   extHi0  = odd ? labHi0 : BLANK;
    const float skipLo0 = (odd && lane >= 3 && labLo0 != labLp0) ? 1.0f : 0.0f;
    const float skipHi0 = (odd && labHi0 != labHp0) ? 1.0f : 0.0f;
    const int   extLo1  = odd ? labLo1 : BLANK;
    const int   extHi1  = odd ? labHi1 : BLANK;
    const float skipLo1 = (odd && lane >= 3 && labLo1 != labLp1) ? 1.0f : 0.0f;
    const float skipHi1 = (odd && labHi1 != labHp1) ? 1.0f : 0.0f;

    // per-lane gather base pointers (fixed column, advance by C_ per row)
    const float* gLo0 = row0 + extLo0;
    const float* gHi0 = row0 + extHi0;
    const float* gTp0 = row0 + BLANK;
    const float* gLo1 = row1 + extLo1;
    const float* gHi1 = row1 + extHi1;
    const float* gTp1 = row1 + BLANK;

    // ---- register prefetch ring: rows 1..8 into slots 0..7
    float bLo0[DEPTH], bHi0[DEPTH], bTp0[DEPTH];
    float bLo1[DEPTH], bHi1[DEPTH], bTp1[DEPTH];
    #pragma unroll
    for (int k = 0; k < DEPTH; ++k) {
        size_t off = (size_t)(1 + k) * C_;
        bLo0[k] = gLo0[off]; bHi0[k] = gHi0[off]; bTp0[k] = gTp0[off];
        bLo1[k] = gLo1[off]; bHi1[k] = gHi1[off]; bTp1[k] = gTp1[off];
    }

    // ---- t = 0 init (tiny direct loads by lanes 0/1)
    float aLo0 = 0.f, aHi0 = 0.f, aTop0 = 0.f;
    float aLo1 = 0.f, aHi1 = 0.f, aTop1 = 0.f;
    if (lane == 0) { aLo0 = row0[BLANK] + EPSF;  aLo1 = row1[BLANK] + EPSF; }
    if (lane == 1) { aLo0 = row0[extLo0] + EPSF; aLo1 = row1[extLo1] + EPSF; }

    float r0 = aLo0, r1 = aLo1;
    #pragma unroll
    for (int d = 16; d; d >>= 1) {
        r0 += __shfl_xor_sync(FULLMASK, r0, d);
        r1 += __shfl_xor_sync(FULLMASK, r1, d);
    }
    float acc0 = __logf(r0),            acc1 = __logf(r1);
    float pend0 = __fdividef(1.0f, r0), pend1 = __fdividef(1.0f, r1);

// One timestep. SLOT, APPLY, REDUCE are compile-time after unrolling
// (t = tb + i with tb == 1 mod 8, so t mod 4 == (1+i) mod 4).
#define STEP(T, SLOT, APPLY, REDUCE)                                          \
    {                                                                         \
        const int _t = (T);                                                   \
        float ic0 = (APPLY) ? pend0 : 1.0f;                                   \
        float ic1 = (APPLY) ? pend1 : 1.0f;                                   \
        float e0 = EPSF * ic0, e1 = EPSF * ic1;                               \
        float pLo0 = fmaf(bLo0[SLOT], ic0, e0);                               \
        float pHi0 = fmaf(bHi0[SLOT], ic0, e0);                               \
        float pTp0 = fmaf(bTp0[SLOT], ic0, e0);                               \
        float pLo1 = fmaf(bLo1[SLOT], ic1, e1);                               \
        float pHi1 = fmaf(bHi1[SLOT], ic1, e1);                               \
        float pTp1 = fmaf(bTp1[SLOT], ic1, e1);                               \
        size_t _off = (size_t)((_t + DEPTH < T_) ? (_t + DEPTH) : (T_ - 1)) * C_; \
        bLo0[SLOT] = gLo0[_off]; bHi0[SLOT] = gHi0[_off]; bTp0[SLOT] = gTp0[_off]; \
        bLo1[SLOT] = gLo1[_off]; bHi1[SLOT] = gHi1[_off]; bTp1[SLOT] = gTp1[_off]; \
        float lo1a = __shfl_up_sync(FULLMASK, aLo0, 1);                       \
        float lo2a = __shfl_up_sync(FULLMASK, aLo0, 2);                       \
        float t31a = __shfl_sync(FULLMASK, aLo0, 31);                         \
        float hi1a = __shfl_up_sync(FULLMASK, aHi0, 1);                       \
        float hi2a = __shfl_up_sync(FULLMASK, aHi0, 2);                       \
        float lo1b = __shfl_up_sync(FULLMASK, aLo1, 1);                       \
        float lo2b = __shfl_up_sync(FULLMASK, aLo1, 2);                       \
        float t31b = __shfl_sync(FULLMASK, aLo1, 31);                         \
        float hi1b = __shfl_up_sync(FULLMASK, aHi1, 1);                       \
        float hi2b = __shfl_up_sync(FULLMASK, aHi1, 2);                       \
        if (lane == 0) { lo1a = 0.f; hi1a = t31a; lo1b = 0.f; hi1b = t31b; }  \
        if (lane == 1) { hi2a = t31a; hi2b = t31b; }                          \
        float nLo0 = fmaf(skipLo0, lo2a, aLo0 + lo1a) * pLo0;                 \
        float nHi0 = fmaf(skipHi0, hi2a, aHi0 + hi1a) * pHi0;                 \
        float nTp0 = (aTop0 + aHi0) * pTp0;                                   \
        float nLo1 = fmaf(skipLo1, lo2b, aLo1 + lo1b) * pLo1;                 \
        float nHi1 = fmaf(skipHi1, hi2b, aHi1 + hi1b) * pHi1;                 \
        float nTp1 = (aTop1 + aHi1) * pTp1;                                   \
        aLo0 = nLo0; aHi0 = nHi0; aTop0 = nTp0;                               \
        aLo1 = nLo1; aHi1 = nHi1; aTop1 = nTp1;                               \
        if (REDUCE) {                                                         \
            float s0 = nLo0 + nHi0 + ((lane == 31) ? nTp0 : 0.f);             \
            float s1 = nLo1 + nHi1 + ((lane == 31) ? nTp1 : 0.f);             \
            _Pragma("unroll")                                                 \
            for (int d = 16; d; d >>= 1) {                                    \
                s0 += __shfl_xor_sync(FULLMASK, s0, d);                       \
                s1 += __shfl_xor_sync(FULLMASK, s1, d);                       \
            }                                                                 \
            acc0 += __logf(s0);                                               \
            acc1 += __logf(s1);                                               \
            pend0 = __fdividef(1.0f, s0);                                     \
            pend1 = __fdividef(1.0f, s1);                                     \
        }                                                                     \
    }

    // main: t = 1..248 in blocks of 8 (tb == 1 mod 8 -> slot i, t mod 4 = (1+i)&3)
    for (int tb = 1; tb + 7 <= 248; tb += 8) {
        #pragma unroll
        for (int i = 0; i < 8; ++i) {
            STEP(tb + i, i, ((1 + i) & 3) == 2, ((1 + i) & 3) == 0);
        }
    }
    // tail: t = 249..255 (249 mod 8 == 1, same slot/phase pattern)
    #pragma unroll
    for (int i = 0; i < 7; ++i) {
        STEP(249 + i, i, ((1 + i) & 3) == 2, ((1 + i) & 3) == 0);
    }
#undef STEP

    // loss = -( log(alpha[S-1] + alpha[S-2]) + sum of applied log-scales )
    if (lane == 31) {
        out[b0] = -(__logf(aTop0 + aHi0) + acc0);
        out[b1] = -(__logf(aTop1 + aHi1) + acc1);
    }
}

extern "C" void kernel_launch(void* const* d_in, const int* in_sizes, int n_in,
                              void* d_out, int out_size) {
    // Identify inputs by size: y_true has B*L elements, y_pred has B*T*C.
    int idx_small = 0, idx_big = 1;
    if (in_sizes[0] > in_sizes[1]) { idx_small = 1; idx_big = 0; }

    const int*   y_true = (const int*)d_in[idx_small];   // int32 view; width detected in-kernel
    const float* y_pred = (const float*)d_in[idx_big];
    float*       out    = (float*)d_out;

    int B = in_sizes[idx_big] / (T_ * C_);   // 1024
    int blocks = B / EPW;                    // 512 one-warp blocks
    ctc_alpha_kernel<<<blocks, 32>>>(y_true, y_pred, out);
}

// round 7
// speedup vs baseline: 1.4662x; 1.4662x over previous
#include <cuda_runtime.h>
#include <cstdint>

#define FULLMASK 0xffffffffu

constexpr int T_ = 256;
constexpr int C_ = 128;
constexpr int L_ = 32;
constexpr int BLANK = 127;   // C-1
constexpr float EPSF = 1e-7f;
constexpr int DEPTH = 8;     // cp.async ring depth

__device__ __forceinline__ uint32_t smem_u32(const void* p) {
    uint32_t a;
    asm("{ .reg .u64 t; cvta.to.shared.u64 t, %1; cvt.u32.u64 %0, t; }"
        : "=r"(a) : "l"(p));
    return a;
}
__device__ __forceinline__ void cp16(uint32_t dst, const float* src) {
    asm volatile("cp.async.cg.shared.global [%0], [%1], 16;"
                 :: "r"(dst), "l"(src) : "memory");
}
#define CP_COMMIT() asm volatile("cp.async.commit_group;" ::: "memory")
#define CP_WAIT7()  asm volatile("cp.async.wait_group 7;" ::: "memory")

// One warp per block; one batch element per warp (maximize resident warps:
// 1024 warps -> ~1.7 warps/SMSP so stalls overlap across warps).
// Lane i owns states s=i (aLo) and s=32+i (aHi); lane 31 also owns s=64 (aTop).
// Probability-domain alphas (fp32), rescale every 4 steps, applied 2 steps later.
// Rows stream coalesced via cp.async into an 8-deep smem ring; the random-column
// gather happens in shared memory (cheap wavefronts), one row ahead of use.
__global__ __launch_bounds__(32)
void ctc_alpha_kernel(const int* __restrict__ y_true_i32,
                      const float* __restrict__ y_pred,
                      float* __restrict__ out)
{
    const int lane = threadIdx.x;          // blockDim.x == 32
    const int b    = blockIdx.x;

    __shared__ float ring[DEPTH][C_];      // 4KB ring of prob rows
    const uint32_t ring_base = smem_u32(&ring[0][0]);

    const float* row = y_pred + (size_t)b * T_ * C_;

    // ---- label dtype detection (int32 vs int64 low-word); first 32 words in-bounds
    int w0 = y_true_i32[lane];
    unsigned zmask = __ballot_sync(FULLMASK, w0 == 0);
    bool is64 = ((zmask & 0xAAAAAAAAu) == 0xAAAAAAAAu);

    int lab = is64 ? y_true_i32[((size_t)b * L_ + lane) * 2]
                   : y_true_i32[(size_t)b * L_ + lane];
    lab &= 127;

    // ---- extended-label class + skip permission
    const bool odd = (lane & 1);
    const int  kLo = (lane >= 1) ? ((lane - 1) >> 1) : 0;
    const int  kLp = (kLo >= 1) ? (kLo - 1) : 0;
    const int  kHi = (31 + lane) >> 1;
    const int  kHp = kHi - 1;

    int labLo = __shfl_sync(FULLMASK, lab, kLo);
    int labLp = __shfl_sync(FULLMASK, lab, kLp);
    int labHi = __shfl_sync(FULLMASK, lab, kHi);
    int labHp = __shfl_sync(FULLMASK, lab, kHp);

    const int   extLo  = odd ? labLo : BLANK;
    const int   extHi  = odd ? labHi : BLANK;
    const float skipLo = (odd && lane >= 3 && labLo != labLp) ? 1.0f : 0.0f;
    const float skipHi = (odd && labHi != labHp) ? 1.0f : 0.0f;

    // ---- prologue: fill ring with rows 1..8 (one commit group per row)
    #pragma unroll
    for (int k = 1; k <= DEPTH; ++k) {
        int slot = k & (DEPTH - 1);
        cp16(ring_base + (slot * C_) * 4 + lane * 16, row + (size_t)k * C_ + lane * 4);
        CP_COMMIT();
    }

    // ---- t = 0 init (tiny direct loads by lanes 0/1)
    float aLo = 0.f, aHi = 0.f, aTop = 0.f;
    if (lane == 0) aLo = row[BLANK] + EPSF;
    if (lane == 1) aLo = row[extLo] + EPSF;

    float r = aLo;
    #pragma unroll
    for (int d = 16; d; d >>= 1) r += __shfl_xor_sync(FULLMASK, r, d);
    float acc  = __logf(r);
    float pend = __fdividef(1.0f, r);

    // ---- gather row 1 probs ahead of the loop
    CP_WAIT7();
    __syncwarp();
    float cLo = ring[1][extLo], cHi = ring[1][extHi], cTp = ring[1][BLANK];

    #pragma unroll 4
    for (int t = 1; t < T_; ++t) {
        // apply (possibly deferred) scale to the pre-gathered probs
        float ic = ((t & 3) == 2) ? pend : 1.0f;
        float e  = EPSF * ic;
        float pLo = fmaf(cLo, ic, e);
        float pHi = fmaf(cHi, ic, e);
        float pTp = fmaf(cTp, ic, e);

        // refill ring: row t+8 into slot t&7 (consumers of that slot long done)
        int tn = (t + DEPTH < T_) ? (t + DEPTH) : (T_ - 1);
        int ws = t & (DEPTH - 1);
        cp16(ring_base + (ws * C_) * 4 + lane * 16, row + (size_t)tn * C_ + lane * 4);
        CP_COMMIT();
        CP_WAIT7();          // row t+1 guaranteed complete
        __syncwarp();

        // gather probs for t+1 (overlaps the alpha chain below)
        int ts = (t + 1 < T_) ? (t + 1) : (T_ - 1);
        const float* g = &ring[ts & (DEPTH - 1)][0];
        cLo = g[extLo]; cHi = g[extHi]; cTp = g[BLANK];

        // neighbor shifts
        float lo1 = __shfl_up_sync(FULLMASK, aLo, 1);
        float lo2 = __shfl_up_sync(FULLMASK, aLo, 2);
        float t31 = __shfl_sync(FULLMASK, aLo, 31);
        float hi1 = __shfl_up_sync(FULLMASK, aHi, 1);
        float hi2 = __shfl_up_sync(FULLMASK, aHi, 2);
        if (lane == 0) { lo1 = 0.f; hi1 = t31; }
        if (lane == 1) { hi2 = t31; }

        float nLo = fmaf(skipLo, lo2, aLo + lo1) * pLo;
        float nHi = fmaf(skipHi, hi2, aHi + hi1) * pHi;
        float nTp = (aTop + aHi) * pTp;
        aLo = nLo; aHi = nHi; aTop = nTp;

        // periodic rescale: reduce at t%4==0, result applied at t+2 (off critical path)
        if ((t & 3) == 0) {
            float s = nLo + nHi + ((lane == 31) ? nTp : 0.f);
            #pragma unroll
            for (int d = 16; d; d >>= 1) s += __shfl_xor_sync(FULLMASK, s, d);
            acc += __logf(s);
            pend = __fdividef(1.0f, s);
        }
    }

    // loss = -( log(alpha[S-1] + alpha[S-2]) + sum of applied log-scales )
    if (lane == 31) {
        out[b] = -(__logf(aTop + aHi) + acc);
    }
}

extern "C" void kernel_launch(void* const* d_in, const int* in_sizes, int n_in,
                              void* d_out, int out_size) {
    // Identify inputs by size: y_true has B*L elements, y_pred has B*T*C.
    int idx_small = 0, idx_big = 1;
    if (in_sizes[0] > in_sizes[1]) { idx_small = 1; idx_big = 0; }

    const int*   y_true = (const int*)d_in[idx_small];   // int32 view; width detected in-kernel
    const float* y_pred = (const float*)d_in[idx_big];
    float*       out    = (float*)d_out;

    int B = in_sizes[idx_big] / (T_ * C_);   // 1024
    ctc_alpha_kernel<<<B, 32>>>(y_true, y_pred, out);
}